// round 1
// baseline (speedup 1.0000x reference)
#include <cuda_runtime.h>
#include <cstddef>

// GraphSage gather + cosine top-16 + mean.
// Inputs (metadata order):
//   d_in[0] nodes  : int32 [N]
//   d_in[1] neigh  : int32 [N, 32]
//   d_in[2] u2e_visual : f32 [500000, 64]
//   d_in[3] u2e_text   : f32 [500000, 64]
// Output: f32 concat(u_v, u_t, v_agg, t_agg), each [N, 64].
//
// One warp per (node, modality). 16 lanes (float4 each) cover one 64-f32 row,
// so each iteration processes 2 neighbors (half-warp each).

#define DEG   32
#define TOPK  16
#define EMB   64

__global__ __launch_bounds__(256) void gs_kernel(
    const int*   __restrict__ nodes,
    const int*   __restrict__ neigh,
    const float* __restrict__ uv,
    const float* __restrict__ ut,
    float*       __restrict__ out,
    int n)
{
    const unsigned FULL = 0xffffffffu;
    int wg = (int)((blockIdx.x * blockDim.x + threadIdx.x) >> 5);
    if (wg >= 2 * n) return;
    int lane = threadIdx.x & 31;
    int node = wg >> 1;
    int m    = wg & 1;
    const float* __restrict__ emb = m ? ut : uv;
    int half = lane >> 4;   // which neighbor of the pair this half-warp handles
    int sub  = lane & 15;   // float4 slot within the 64-float row

    // ---- center gather + write-through ----
    int cidx = __ldg(nodes + node);
    float4 u4 = __ldg((const float4*)(emb + (size_t)cidx * EMB) + sub);

    size_t nn = (size_t)n * EMB;
    float* cout = out + (size_t)m * nn + (size_t)node * EMB;
    if (half == 0) ((float4*)cout)[sub] = u4;

    // ---- neighbor indices: lane k holds neigh[node][k] ----
    int nidx = __ldg(neigh + (size_t)node * DEG + lane);

    // ---- similarities: dot(u, v_k) / (||v_k|| + eps); center norm is a
    //      positive constant factor and does not affect the top-k ordering ----
    float tmp = 0.0f;
    #pragma unroll
    for (int k = 0; k < DEG; k += 2) {
        int j = __shfl_sync(FULL, nidx, k + half);
        float4 v = __ldg((const float4*)(emb + (size_t)j * EMB) + sub);
        float dot = v.x * u4.x + v.y * u4.y + v.z * u4.z + v.w * u4.w;
        float nsq = v.x * v.x + v.y * v.y + v.z * v.z + v.w * v.w;
        #pragma unroll
        for (int s = 8; s; s >>= 1) {            // butterfly within each half-warp
            dot += __shfl_xor_sync(FULL, dot, s);
            nsq += __shfl_xor_sync(FULL, nsq, s);
        }
        float sim = dot / (sqrtf(nsq) + 1e-8f);
        if (sub == (k >> 1)) tmp = sim;          // lane 16*half + k/2 keeps sim(k+half)
    }
    // Redistribute so lane L holds sim(L):
    // sim(i) lives at lane 16*(i&1) + (i>>1)  =>  src(L) = ((L&1)<<4) | (L>>1)
    float mysim = __shfl_sync(FULL, tmp, ((lane & 1) << 4) | (lane >> 1));

    // ---- stable top-16 via rank count (matches jax.lax.top_k tie-break) ----
    int cnt = 0;
    #pragma unroll
    for (int jl = 0; jl < DEG; jl++) {
        float o = __shfl_sync(FULL, mysim, jl);
        cnt += (o > mysim) || (o == mysim && jl < lane);
    }
    unsigned sel = __ballot_sync(FULL, cnt < TOPK);   // exactly TOPK bits set

    // ---- mean of selected rows (re-reads hit L1: same warp just read them) ----
    float4 acc = make_float4(0.f, 0.f, 0.f, 0.f);
    #pragma unroll
    for (int k = 0; k < DEG; k += 2) {
        int kk = k + half;
        int j = __shfl_sync(FULL, nidx, kk);
        if (sel & (1u << kk)) {
            float4 v = __ldg((const float4*)(emb + (size_t)j * EMB) + sub);
            acc.x += v.x; acc.y += v.y; acc.z += v.z; acc.w += v.w;
        }
    }
    // combine the even-neighbor half with the odd-neighbor half
    acc.x += __shfl_xor_sync(FULL, acc.x, 16);
    acc.y += __shfl_xor_sync(FULL, acc.y, 16);
    acc.z += __shfl_xor_sync(FULL, acc.z, 16);
    acc.w += __shfl_xor_sync(FULL, acc.w, 16);

    float* aout = out + (size_t)(2 + m) * nn + (size_t)node * EMB;
    if (half == 0) {
        const float s = 1.0f / (float)TOPK;
        float4 r = make_float4(acc.x * s, acc.y * s, acc.z * s, acc.w * s);
        ((float4*)aout)[sub] = r;
    }
}

extern "C" void kernel_launch(void* const* d_in, const int* in_sizes, int n_in,
                              void* d_out, int out_size) {
    const int*   nodes = (const int*)d_in[0];
    const int*   neigh = (const int*)d_in[1];
    const float* uv    = (const float*)d_in[2];
    const float* ut    = (const float*)d_in[3];
    float*       out   = (float*)d_out;
    int n = in_sizes[0];                 // number of nodes
    int warps = 2 * n;                   // (node, modality) tasks
    int threads = 256;
    int blocks = (warps * 32 + threads - 1) / threads;
    gs_kernel<<<blocks, threads>>>(nodes, neigh, uv, ut, out, n);
}

// round 2
// speedup vs baseline: 1.4953x; 1.4953x over previous
#include <cuda_runtime.h>
#include <cstddef>

// GraphSage gather + cosine top-16 + mean.  (Round 2)
//   d_in[0] nodes  : int32 [N]
//   d_in[1] neigh  : int32 [N, 32]
//   d_in[2] u2e_visual : f32 [500000, 64]
//   d_in[3] u2e_text   : f32 [500000, 64]
// Output: f32 concat(u_v, u_t, v_agg, t_agg), each [N, 64].
//
// One warp per (node, modality). Task order is modality-major (all visual
// tasks first, then all text) so each phase's random-gather working set is a
// single 128 MB table, which ~fits the 126 MB L2.
//
// Sim loop: 8-lane groups (4 neighbors per warp-iteration, 3-step butterfly).
// Mean loop: 16-lane halves (no per-neighbor reduction needed; 4-shfl combine).

#define DEG   32
#define TOPK  16
#define EMB   64

__global__ __launch_bounds__(256) void gs_kernel(
    const int*   __restrict__ nodes,
    const int*   __restrict__ neigh,
    const float* __restrict__ uv,
    const float* __restrict__ ut,
    float*       __restrict__ out,
    int n)
{
    const unsigned FULL = 0xffffffffu;
    int wg = (int)((blockIdx.x * blockDim.x + threadIdx.x) >> 5);
    if (wg >= 2 * n) return;
    int lane = threadIdx.x & 31;

    // modality-major task order: [0,n) = visual, [n,2n) = text
    int m    = (wg >= n) ? 1 : 0;
    int node = wg - m * n;
    const float* __restrict__ emb = m ? ut : uv;

    int g = lane >> 3;     // 8-lane group id (0..3) — one neighbor per group
    int s = lane & 7;      // sub-lane within group — 8 floats per lane

    // ---- center gather (8-lane layout: lane s holds float4 s and s+8) ----
    int cidx = __ldg(nodes + node);
    const float4* crow = (const float4*)(emb + (size_t)cidx * EMB);
    float4 ua = __ldg(crow + s);
    float4 ub = __ldg(crow + s + 8);

    size_t nn = (size_t)n * EMB;
    float4* cout = (float4*)(out + (size_t)m * nn + (size_t)node * EMB);
    if (g == 0) { cout[s] = ua; cout[s + 8] = ub; }

    // ---- neighbor indices: lane k holds neigh[node][k] ----
    int nidx = __ldg(neigh + (size_t)node * DEG + lane);

    // ---- similarities: dot(u,v)/(||v||+eps); center norm is a positive
    //      per-node constant, irrelevant to the ordering ----
    float tmp = 0.0f;
    #pragma unroll
    for (int it = 0; it < 8; it++) {
        int j = __shfl_sync(FULL, nidx, 4 * it + g);
        const float4* vrow = (const float4*)(emb + (size_t)j * EMB);
        float4 va = __ldg(vrow + s);
        float4 vb = __ldg(vrow + s + 8);
        float dot = va.x * ua.x + va.y * ua.y + va.z * ua.z + va.w * ua.w
                  + vb.x * ub.x + vb.y * ub.y + vb.z * ub.z + vb.w * ub.w;
        float nsq = va.x * va.x + va.y * va.y + va.z * va.z + va.w * va.w
                  + vb.x * vb.x + vb.y * vb.y + vb.z * vb.z + vb.w * vb.w;
        #pragma unroll
        for (int d = 1; d < 8; d <<= 1) {        // 3-step butterfly in each group
            dot += __shfl_xor_sync(FULL, dot, d);
            nsq += __shfl_xor_sync(FULL, nsq, d);
        }
        float sim = dot / (sqrtf(nsq) + 1e-8f);
        if (s == it) tmp = sim;                  // lane L holds sim(4*(L&7)+(L>>3))
    }
    // redistribute so lane j holds sim(j): src(j) = ((j&3)<<3) | (j>>2)
    float mysim = __shfl_sync(FULL, tmp, ((lane & 3) << 3) | (lane >> 2));

    // ---- stable top-16 via rank count (matches jax.lax.top_k tie-break) ----
    int cnt = 0;
    #pragma unroll
    for (int jl = 0; jl < DEG; jl++) {
        float o = __shfl_sync(FULL, mysim, jl);
        cnt += (o > mysim) || (o == mysim && jl < lane);
    }
    unsigned sel = __ballot_sync(FULL, cnt < TOPK);   // exactly TOPK bits set

    // ---- mean of selected (unnormalized) rows; re-reads hit L1 ----
    int half = lane >> 4;   // 16-lane halves: 2 neighbors per iteration
    int sub  = lane & 15;
    float4 acc = make_float4(0.f, 0.f, 0.f, 0.f);
    #pragma unroll
    for (int k = 0; k < DEG; k += 2) {
        int kk = k + half;
        int j = __shfl_sync(FULL, nidx, kk);
        if (sel & (1u << kk)) {
            float4 v = __ldg((const float4*)(emb + (size_t)j * EMB) + sub);
            acc.x += v.x; acc.y += v.y; acc.z += v.z; acc.w += v.w;
        }
    }
    acc.x += __shfl_xor_sync(FULL, acc.x, 16);
    acc.y += __shfl_xor_sync(FULL, acc.y, 16);
    acc.z += __shfl_xor_sync(FULL, acc.z, 16);
    acc.w += __shfl_xor_sync(FULL, acc.w, 16);

    if (half == 0) {
        const float sc = 1.0f / (float)TOPK;
        float4 r = make_float4(acc.x * sc, acc.y * sc, acc.z * sc, acc.w * sc);
        float4* aout = (float4*)(out + (size_t)(2 + m) * nn + (size_t)node * EMB);
        aout[sub] = r;
    }
}

extern "C" void kernel_launch(void* const* d_in, const int* in_sizes, int n_in,
                              void* d_out, int out_size) {
    const int*   nodes = (const int*)d_in[0];
    const int*   neigh = (const int*)d_in[1];
    const float* uv    = (const float*)d_in[2];
    const float* ut    = (const float*)d_in[3];
    float*       out   = (float*)d_out;
    int n = in_sizes[0];
    int warps = 2 * n;
    int threads = 256;
    int blocks = (warps * 32 + threads - 1) / threads;
    gs_kernel<<<blocks, threads>>>(nodes, neigh, uv, ut, out, n);
}

// round 3
// speedup vs baseline: 1.6262x; 1.0876x over previous
#include <cuda_runtime.h>
#include <cstddef>

// GraphSage gather + cosine top-16 + mean.  (Round 3)
//   d_in[0] nodes  : int32 [N]
//   d_in[1] neigh  : int32 [N, 32]
//   d_in[2] u2e_visual : f32 [500000, 64]
//   d_in[3] u2e_text   : f32 [500000, 64]
// Output: f32 concat(u_v, u_t, v_agg, t_agg), each [N, 64].
//
// One warp per (node, modality), modality-major order (single-table L2 phase).
// Sim loop: 8-lane groups (4 neighbors/iter, full-line LDG.128s).
// Ranking uses the strictly-monotone transform dot*|dot|/||v||^2 (no sqrt).
// Mean loop: 16-lane halves over the top-16 rows (L1-resident re-reads).
// Outputs/index streams use evict-first cache hints to protect L2 residency
// of the embedding table.

#define DEG   32
#define TOPK  16
#define EMB   64

__global__ __launch_bounds__(256, 7) void gs_kernel(
    const int*   __restrict__ nodes,
    const int*   __restrict__ neigh,
    const float* __restrict__ uv,
    const float* __restrict__ ut,
    float*       __restrict__ out,
    int n)
{
    const unsigned FULL = 0xffffffffu;
    int wg = (int)((blockIdx.x * blockDim.x + threadIdx.x) >> 5);
    if (wg >= 2 * n) return;
    int lane = threadIdx.x & 31;

    // modality-major task order: [0,n) = visual, [n,2n) = text
    int m    = (wg >= n) ? 1 : 0;
    int node = wg - m * n;
    const float* __restrict__ emb = m ? ut : uv;

    int g = lane >> 3;     // 8-lane group id (0..3) — one neighbor per group
    int s = lane & 7;      // sub-lane within group — 8 floats per lane

    // ---- center gather (lane s holds float4 s and s+8 of the row) ----
    int cidx = __ldcs(nodes + node);
    const float4* crow = (const float4*)(emb + (size_t)cidx * EMB);
    float4 ua = __ldg(crow + s);
    float4 ub = __ldg(crow + s + 8);

    size_t nn = (size_t)n * EMB;
    float4* cout = (float4*)(out + (size_t)m * nn + (size_t)node * EMB);
    if (g == 0) { __stcs(cout + s, ua); __stcs(cout + s + 8, ub); }

    // ---- neighbor indices: lane k holds neigh[node][k] ----
    int nidx = __ldcs(neigh + (size_t)node * DEG + lane);

    // ---- ranking value: dot*|dot|/||v||^2  (strictly monotone in cosine;
    //      center norm is a positive per-node constant, irrelevant) ----
    float tmp = 0.0f;
    #pragma unroll
    for (int it = 0; it < 8; it++) {
        int j = __shfl_sync(FULL, nidx, 4 * it + g);
        const float4* vrow = (const float4*)(emb + (size_t)j * EMB);
        float4 va = __ldg(vrow + s);
        float4 vb = __ldg(vrow + s + 8);
        float dot = va.x * ua.x + va.y * ua.y + va.z * ua.z + va.w * ua.w
                  + vb.x * ub.x + vb.y * ub.y + vb.z * ub.z + vb.w * ub.w;
        float nsq = va.x * va.x + va.y * va.y + va.z * va.z + va.w * va.w
                  + vb.x * vb.x + vb.y * vb.y + vb.z * vb.z + vb.w * vb.w;
        #pragma unroll
        for (int d = 1; d < 8; d <<= 1) {        // 3-step butterfly per group
            dot += __shfl_xor_sync(FULL, dot, d);
            nsq += __shfl_xor_sync(FULL, nsq, d);
        }
        float r = __fdividef(dot * fabsf(dot), nsq + 1e-20f);
        if (s == it) tmp = r;                    // lane L holds r(4*(L&7)+(L>>3))
    }
    // redistribute so lane j holds r(j): src(j) = ((j&3)<<3) | (j>>2)
    float mysim = __shfl_sync(FULL, tmp, ((lane & 3) << 3) | (lane >> 2));

    // ---- stable top-16 via rank count (matches jax.lax.top_k tie-break) ----
    int cnt = 0;
    #pragma unroll
    for (int jl = 0; jl < DEG; jl++) {
        float o = __shfl_sync(FULL, mysim, jl);
        cnt += (o > mysim) || (o == mysim && jl < lane);
    }
    unsigned sel = __ballot_sync(FULL, cnt < TOPK);   // exactly TOPK bits set

    // ---- mean of selected (unnormalized) rows; re-reads hit L1 ----
    int half = lane >> 4;   // 16-lane halves: 2 neighbors per iteration
    int sub  = lane & 15;
    float4 acc = make_float4(0.f, 0.f, 0.f, 0.f);
    #pragma unroll
    for (int k = 0; k < DEG; k += 2) {
        int kk = k + half;
        int j = __shfl_sync(FULL, nidx, kk);
        if (sel & (1u << kk)) {
            float4 v = __ldg((const float4*)(emb + (size_t)j * EMB) + sub);
            acc.x += v.x; acc.y += v.y; acc.z += v.z; acc.w += v.w;
        }
    }
    acc.x += __shfl_xor_sync(FULL, acc.x, 16);
    acc.y += __shfl_xor_sync(FULL, acc.y, 16);
    acc.z += __shfl_xor_sync(FULL, acc.z, 16);
    acc.w += __shfl_xor_sync(FULL, acc.w, 16);

    if (half == 0) {
        const float sc = 1.0f / (float)TOPK;
        float4 r = make_float4(acc.x * sc, acc.y * sc, acc.z * sc, acc.w * sc);
        float4* aout = (float4*)(out + (size_t)(2 + m) * nn + (size_t)node * EMB);
        __stcs(aout + sub, r);
    }
}

extern "C" void kernel_launch(void* const* d_in, const int* in_sizes, int n_in,
                              void* d_out, int out_size) {
    const int*   nodes = (const int*)d_in[0];
    const int*   neigh = (const int*)d_in[1];
    const float* uv    = (const float*)d_in[2];
    const float* ut    = (const float*)d_in[3];
    float*       out   = (float*)d_out;
    int n = in_sizes[0];
    int warps = 2 * n;
    int threads = 256;
    int blocks = (warps * 32 + threads - 1) / threads;
    gs_kernel<<<blocks, threads>>>(nodes, neigh, uv, ut, out, n);
}